// round 5
// baseline (speedup 1.0000x reference)
#include <cuda_runtime.h>
#include <math.h>

#define SAMPLE_RATE 44100.0f
#define R_PARAM 0.5f
#define F_PARAM 1000.0f

// Single fused kernel.
//  Phase 1: thread 0 of each block builds the fused affine map
//        x_n = M x_n1 + va u_n + vb u_n1,   y = gain * x_n[3]
//    (M = inv(I - kA/2*alpha) @ (I + kA - kA/2*alpha), Gauss-Jordan;
//     system is I + O(0.1), diagonally dominant -> no pivoting) into smem.
//  Phase 2 (after barrier): each thread handles 4 samples strided by 32
//    within its warp: sample(s) = warp*128 + s*32 + lane -> every LDG/STG
//    instruction is perfectly coalesced (x: 512B full lines; u/u1/y: 128B).
//  All traffic is streaming -> __ldcs/__stcs (evict-first).
// Output layout (out_size = 6*B floats): [0,B) y | [B,5B) x | [5B,6B) u
__device__ __noinline__ void build_consts(float* sc,
                                          const float* p_gf, const float* p_gr,
                                          const float* p_gain, const float* p_alpha) {
    float GF = p_gf[0];
    float GR = p_gr[0];
    float GAIN = p_gain[0];
    float AL = p_alpha[0];

    float k = 1.0f / SAMPLE_RATE;
    float w = 2.0f * 3.14159265358979323846f * GF * F_PARAM;

    float A[4][4] = {
        {-w, 0.0f, 0.0f, -4.0f * w * GR * R_PARAM},
        { w,  -w, 0.0f, 0.0f},
        {0.0f,  w,  -w, 0.0f},
        {0.0f, 0.0f,  w,  -w}
    };

    // Augmented: L * [M | va | vb] = [F | b_a | b_1ma]  (4 x 10)
    float aug[4][10];
#pragma unroll
    for (int i = 0; i < 4; i++) {
#pragma unroll
        for (int j = 0; j < 4; j++) {
            float kA2 = 0.5f * k * A[i][j];
            float I = (i == j) ? 1.0f : 0.0f;
            aug[i][j]     = I - kA2 * AL;            // L
            aug[i][4 + j] = I + kA2 * (2.0f - AL);   // F
        }
        aug[i][8] = 0.0f;
        aug[i][9] = 0.0f;
    }
    float kb2 = 0.5f * k * w;
    aug[0][8] = kb2 * AL;                 // b_a
    aug[0][9] = kb2 * (1.0f - AL * 0.5f); // b_1ma

#pragma unroll
    for (int c = 0; c < 4; c++) {
        float inv = 1.0f / aug[c][c];
#pragma unroll
        for (int j = 0; j < 10; j++) aug[c][j] *= inv;
#pragma unroll
        for (int r = 0; r < 4; r++) {
            if (r == c) continue;
            float f = aug[r][c];
#pragma unroll
            for (int j = 0; j < 10; j++) aug[r][j] -= f * aug[c][j];
        }
    }

#pragma unroll
    for (int i = 0; i < 4; i++)
#pragma unroll
        for (int j = 0; j < 4; j++)
            sc[i * 4 + j] = aug[i][4 + j];           // M
#pragma unroll
    for (int i = 0; i < 4; i++) sc[16 + i] = aug[i][8];   // va
#pragma unroll
    for (int i = 0; i < 4; i++) sc[20 + i] = aug[i][9];   // vb
    sc[24] = GAIN;
}

__global__ __launch_bounds__(256)
void moog_fused_kernel(const float* __restrict__ u,
                       const float4* __restrict__ x1,
                       const float* __restrict__ u1,
                       const float* __restrict__ p_gf,
                       const float* __restrict__ p_gr,
                       const float* __restrict__ p_gain,
                       const float* __restrict__ p_alpha,
                       float* __restrict__ out, int B) {
    __shared__ __align__(16) float sc[28];

    if (threadIdx.x == 0)
        build_consts(sc, p_gf, p_gr, p_gain, p_alpha);
    __syncthreads();

    int tid = blockIdx.x * blockDim.x + threadIdx.x;
    int warp = tid >> 5;
    int lane = tid & 31;
    int base = warp * 128 + lane;            // sample index for s=0
    if (base + 96 >= B) return;              // B is a multiple of 128

    const float4* c4 = (const float4*)sc;
    float4 m0 = c4[0], m1 = c4[1], m2 = c4[2], m3 = c4[3];
    float4 va = c4[4], vb = c4[5];
    float gain = sc[24];

    float4* x_out = (float4*)(out + (size_t)B);
    float*  u_out = out + (size_t)5 * B;
    float*  y_out = out;

    // Batch all loads first for max MLP (streaming, evict-first)
    float4 xv[4];
    float uu[4], uu1[4];
#pragma unroll
    for (int s = 0; s < 4; s++) {
        int idx = base + 32 * s;
        xv[s]  = __ldcs(&x1[idx]);
        uu[s]  = __ldcs(&u[idx]);
        uu1[s] = __ldcs(&u1[idx]);
    }

#pragma unroll
    for (int s = 0; s < 4; s++) {
        int idx = base + 32 * s;
        float4 x = xv[s];
        float x0n = fmaf(m0.x, x.x, fmaf(m0.y, x.y, fmaf(m0.z, x.z,
                    fmaf(m0.w, x.w, fmaf(va.x, uu[s], vb.x * uu1[s])))));
        float x1n = fmaf(m1.x, x.x, fmaf(m1.y, x.y, fmaf(m1.z, x.z,
                    fmaf(m1.w, x.w, fmaf(va.y, uu[s], vb.y * uu1[s])))));
        float x2n = fmaf(m2.x, x.x, fmaf(m2.y, x.y, fmaf(m2.z, x.z,
                    fmaf(m2.w, x.w, fmaf(va.z, uu[s], vb.z * uu1[s])))));
        float x3n = fmaf(m3.x, x.x, fmaf(m3.y, x.y, fmaf(m3.z, x.z,
                    fmaf(m3.w, x.w, fmaf(va.w, uu[s], vb.w * uu1[s])))));
        __stcs(&x_out[idx], make_float4(x0n, x1n, x2n, x3n));
        __stcs(&y_out[idx], gain * x3n);
        __stcs(&u_out[idx], uu[s]);
    }
}

extern "C" void kernel_launch(void* const* d_in, const int* in_sizes, int n_in,
                              void* d_out, int out_size) {
    const float* u_n   = (const float*)d_in[0];
    const float* x_n1  = (const float*)d_in[1];
    const float* u_n1  = (const float*)d_in[2];
    const float* gf    = (const float*)d_in[3];
    const float* gr    = (const float*)d_in[4];
    const float* gain  = (const float*)d_in[5];
    const float* alpha = (const float*)d_in[6];
    float* out = (float*)d_out;

    int B = in_sizes[0];

    int threads = 256;
    int total_threads = B / 4;           // 4 samples per thread
    int blocks = (total_threads + threads - 1) / threads;
    moog_fused_kernel<<<blocks, threads>>>(u_n, (const float4*)x_n1, u_n1,
                                           gf, gr, gain, alpha, out, B);
}

// round 6
// speedup vs baseline: 1.0073x; 1.0073x over previous
#include <cuda_runtime.h>
#include <math.h>

#define SAMPLE_RATE 44100.0f
#define R_PARAM 0.5f
#define F_PARAM 1000.0f

// Single fused kernel.
//  Phase 1: thread 0 of each block builds the fused affine map
//        x_n = M x_n1 + va u_n + vb u_n1,   y = gain * x_n[3]
//    (M = inv(I - kA/2*alpha) @ (I + kA - kA/2*alpha), Gauss-Jordan;
//     system is I + O(0.1), diagonally dominant -> no pivoting) into smem.
//  Phase 2 (after barrier): each thread handles 4 samples strided by 32
//    within its warp: sample(s) = warp*128 + s*32 + lane -> every LDG/STG
//    instruction is perfectly coalesced (x: 512B full lines; u/u1/y: 128B).
//  All traffic is streaming -> __ldcs/__stcs (evict-first).
// Output layout (out_size = 6*B floats): [0,B) y | [B,5B) x | [5B,6B) u
__device__ __noinline__ void build_consts(float* sc,
                                          const float* p_gf, const float* p_gr,
                                          const float* p_gain, const float* p_alpha) {
    float GF = p_gf[0];
    float GR = p_gr[0];
    float GAIN = p_gain[0];
    float AL = p_alpha[0];

    float k = 1.0f / SAMPLE_RATE;
    float w = 2.0f * 3.14159265358979323846f * GF * F_PARAM;

    float A[4][4] = {
        {-w, 0.0f, 0.0f, -4.0f * w * GR * R_PARAM},
        { w,  -w, 0.0f, 0.0f},
        {0.0f,  w,  -w, 0.0f},
        {0.0f, 0.0f,  w,  -w}
    };

    // Augmented: L * [M | va | vb] = [F | b_a | b_1ma]  (4 x 10)
    float aug[4][10];
#pragma unroll
    for (int i = 0; i < 4; i++) {
#pragma unroll
        for (int j = 0; j < 4; j++) {
            float kA2 = 0.5f * k * A[i][j];
            float I = (i == j) ? 1.0f : 0.0f;
            aug[i][j]     = I - kA2 * AL;            // L
            aug[i][4 + j] = I + kA2 * (2.0f - AL);   // F
        }
        aug[i][8] = 0.0f;
        aug[i][9] = 0.0f;
    }
    float kb2 = 0.5f * k * w;
    aug[0][8] = kb2 * AL;                 // b_a
    aug[0][9] = kb2 * (1.0f - AL * 0.5f); // b_1ma

#pragma unroll
    for (int c = 0; c < 4; c++) {
        float inv = 1.0f / aug[c][c];
#pragma unroll
        for (int j = 0; j < 10; j++) aug[c][j] *= inv;
#pragma unroll
        for (int r = 0; r < 4; r++) {
            if (r == c) continue;
            float f = aug[r][c];
#pragma unroll
            for (int j = 0; j < 10; j++) aug[r][j] -= f * aug[c][j];
        }
    }

#pragma unroll
    for (int i = 0; i < 4; i++)
#pragma unroll
        for (int j = 0; j < 4; j++)
            sc[i * 4 + j] = aug[i][4 + j];           // M
#pragma unroll
    for (int i = 0; i < 4; i++) sc[16 + i] = aug[i][8];   // va
#pragma unroll
    for (int i = 0; i < 4; i++) sc[20 + i] = aug[i][9];   // vb
    sc[24] = GAIN;
}

__global__ __launch_bounds__(256)
void moog_fused_kernel(const float* __restrict__ u,
                       const float4* __restrict__ x1,
                       const float* __restrict__ u1,
                       const float* __restrict__ p_gf,
                       const float* __restrict__ p_gr,
                       const float* __restrict__ p_gain,
                       const float* __restrict__ p_alpha,
                       float* __restrict__ out, int B) {
    __shared__ __align__(16) float sc[28];

    if (threadIdx.x == 0)
        build_consts(sc, p_gf, p_gr, p_gain, p_alpha);
    __syncthreads();

    int tid = blockIdx.x * blockDim.x + threadIdx.x;
    int warp = tid >> 5;
    int lane = tid & 31;
    int base = warp * 128 + lane;            // sample index for s=0
    if (base + 96 >= B) return;              // B is a multiple of 128

    const float4* c4 = (const float4*)sc;
    float4 m0 = c4[0], m1 = c4[1], m2 = c4[2], m3 = c4[3];
    float4 va = c4[4], vb = c4[5];
    float gain = sc[24];

    float4* x_out = (float4*)(out + (size_t)B);
    float*  u_out = out + (size_t)5 * B;
    float*  y_out = out;

    // Batch all loads first for max MLP (streaming, evict-first)
    float4 xv[4];
    float uu[4], uu1[4];
#pragma unroll
    for (int s = 0; s < 4; s++) {
        int idx = base + 32 * s;
        xv[s]  = __ldcs(&x1[idx]);
        uu[s]  = __ldcs(&u[idx]);
        uu1[s] = __ldcs(&u1[idx]);
    }

#pragma unroll
    for (int s = 0; s < 4; s++) {
        int idx = base + 32 * s;
        float4 x = xv[s];
        float x0n = fmaf(m0.x, x.x, fmaf(m0.y, x.y, fmaf(m0.z, x.z,
                    fmaf(m0.w, x.w, fmaf(va.x, uu[s], vb.x * uu1[s])))));
        float x1n = fmaf(m1.x, x.x, fmaf(m1.y, x.y, fmaf(m1.z, x.z,
                    fmaf(m1.w, x.w, fmaf(va.y, uu[s], vb.y * uu1[s])))));
        float x2n = fmaf(m2.x, x.x, fmaf(m2.y, x.y, fmaf(m2.z, x.z,
                    fmaf(m2.w, x.w, fmaf(va.z, uu[s], vb.z * uu1[s])))));
        float x3n = fmaf(m3.x, x.x, fmaf(m3.y, x.y, fmaf(m3.z, x.z,
                    fmaf(m3.w, x.w, fmaf(va.w, uu[s], vb.w * uu1[s])))));
        __stcs(&x_out[idx], make_float4(x0n, x1n, x2n, x3n));
        __stcs(&y_out[idx], gain * x3n);
        __stcs(&u_out[idx], uu[s]);
    }
}

extern "C" void kernel_launch(void* const* d_in, const int* in_sizes, int n_in,
                              void* d_out, int out_size) {
    const float* u_n   = (const float*)d_in[0];
    const float* x_n1  = (const float*)d_in[1];
    const float* u_n1  = (const float*)d_in[2];
    const float* gf    = (const float*)d_in[3];
    const float* gr    = (const float*)d_in[4];
    const float* gain  = (const float*)d_in[5];
    const float* alpha = (const float*)d_in[6];
    float* out = (float*)d_out;

    int B = in_sizes[0];

    int threads = 256;
    int total_threads = B / 4;           // 4 samples per thread
    int blocks = (total_threads + threads - 1) / threads;
    moog_fused_kernel<<<blocks, threads>>>(u_n, (const float4*)x_n1, u_n1,
                                           gf, gr, gain, alpha, out, B);
}